// round 1
// baseline (speedup 1.0000x reference)
#include <cuda_runtime.h>
#include <math.h>

#define Bsz 4
#define Lsz 1024
#define Dsz 512
#define Hsz 8
#define DKsz 64

// ---------------- scratch (static device globals; no allocation) ----------------
__device__ float g_Q[Bsz*Lsz*Dsz];      // projected q  (B,L,D)
__device__ float g_K[Bsz*Lsz*Dsz];      // projected k
__device__ float g_V[Bsz*Lsz*Dsz];      // projected v
__device__ float g_QP[Bsz*Lsz*Dsz];     // mask-perturb q proj
__device__ float g_KP[Bsz*Lsz*Dsz];     // mask-perturb k proj
__device__ float g_EM[Bsz*Lsz*Lsz];     // exp(1 - m)
__device__ float g_G[Bsz*Lsz];          // gate
__device__ float g_S[(size_t)Bsz*Hsz*Lsz*Lsz]; // scores / attn (134MB)
__device__ float g_CTX[Bsz*Lsz*Dsz];    // attention output before dense

// ---------------- generic NN GEMM: C = A(MxK) @ W(KxN) + bias ----------------
__global__ void gemm_nn_bias_kernel(const float* __restrict__ A,
                                    const float* __restrict__ W,
                                    const float* __restrict__ bias,
                                    float* __restrict__ C,
                                    int M, int N, int K)
{
    __shared__ float As[64][33];
    __shared__ float Ws[32][65];
    int tid = threadIdx.x;
    int tx = tid & 15, ty = tid >> 4;
    int row0 = blockIdx.y * 64;
    int col0 = blockIdx.x * 64;
    float acc[4][4] = {};

    for (int kk0 = 0; kk0 < K; kk0 += 32) {
        {
            int c = tid & 31, r = tid >> 5;
            #pragma unroll
            for (int i = 0; i < 8; i++)
                As[r + i*8][c] = A[(size_t)(row0 + r + i*8) * K + kk0 + c];
        }
        {
            int c = tid & 63, r = tid >> 6;
            #pragma unroll
            for (int i = 0; i < 8; i++)
                Ws[r + i*4][c] = W[(size_t)(kk0 + r + i*4) * N + col0 + c];
        }
        __syncthreads();
        #pragma unroll
        for (int kk = 0; kk < 32; kk++) {
            float a[4], b[4];
            #pragma unroll
            for (int i = 0; i < 4; i++) a[i] = As[ty*4 + i][kk];
            #pragma unroll
            for (int j = 0; j < 4; j++) b[j] = Ws[kk][tx*4 + j];
            #pragma unroll
            for (int i = 0; i < 4; i++)
                #pragma unroll
                for (int j = 0; j < 4; j++)
                    acc[i][j] += a[i] * b[j];
        }
        __syncthreads();
    }
    #pragma unroll
    for (int i = 0; i < 4; i++) {
        int row = row0 + ty*4 + i;
        #pragma unroll
        for (int j = 0; j < 4; j++) {
            int col = col0 + tx*4 + j;
            C[(size_t)row * N + col] = acc[i][j] + bias[col];
        }
    }
}

// ---------------- m GEMM (NT, per batch): m = sigmoid(QP @ KP^T / sqrt(D)) ----------------
__global__ void m_gemm_kernel(float* __restrict__ m_out)
{
    const float SCALE = 0.04419417382415922f; // 1/sqrt(512)
    int zb = blockIdx.z;
    const float* Ap = g_QP + (size_t)zb * Lsz * Dsz;
    const float* Bp = g_KP + (size_t)zb * Lsz * Dsz;
    float* Mo = m_out + (size_t)zb * Lsz * Lsz;
    float* Eo = g_EM  + (size_t)zb * Lsz * Lsz;

    __shared__ float As[64][33];
    __shared__ float Bs[64][33];
    int tid = threadIdx.x;
    int tx = tid & 15, ty = tid >> 4;
    int row0 = blockIdx.y * 64;
    int col0 = blockIdx.x * 64;
    float acc[4][4] = {};

    for (int kk0 = 0; kk0 < Dsz; kk0 += 32) {
        int c = tid & 31, r = tid >> 5;
        #pragma unroll
        for (int i = 0; i < 8; i++)
            As[r + i*8][c] = Ap[(size_t)(row0 + r + i*8) * Dsz + kk0 + c];
        #pragma unroll
        for (int i = 0; i < 8; i++)
            Bs[r + i*8][c] = Bp[(size_t)(col0 + r + i*8) * Dsz + kk0 + c];
        __syncthreads();
        #pragma unroll
        for (int kk = 0; kk < 32; kk++) {
            float a[4], b[4];
            #pragma unroll
            for (int i = 0; i < 4; i++) a[i] = As[ty*4 + i][kk];
            #pragma unroll
            for (int j = 0; j < 4; j++) b[j] = Bs[tx*4 + j][kk];
            #pragma unroll
            for (int i = 0; i < 4; i++)
                #pragma unroll
                for (int j = 0; j < 4; j++)
                    acc[i][j] += a[i] * b[j];
        }
        __syncthreads();
    }
    #pragma unroll
    for (int i = 0; i < 4; i++) {
        int row = row0 + ty*4 + i;
        #pragma unroll
        for (int j = 0; j < 4; j++) {
            int col = col0 + tx*4 + j;
            float s = 1.0f / (1.0f + expf(-acc[i][j] * SCALE));
            Mo[(size_t)row * Lsz + col] = s;
            Eo[(size_t)row * Lsz + col] = expf(1.0f - s);
        }
    }
}

// ---------------- scores GEMM (NT, per (b,h)): S = Qh @ Kh^T / sqrt(DK) ----------------
__global__ void score_gemm_kernel()
{
    const float SCALE = 0.125f; // 1/sqrt(64)
    int z = blockIdx.z;          // b*H + h
    int b = z >> 3, h = z & 7;
    const float* Ap = g_Q + (size_t)b * Lsz * Dsz + h * DKsz;
    const float* Bp = g_K + (size_t)b * Lsz * Dsz + h * DKsz;
    float* Cp = g_S + (size_t)z * Lsz * Lsz;

    __shared__ float As[64][33];
    __shared__ float Bs[64][33];
    int tid = threadIdx.x;
    int tx = tid & 15, ty = tid >> 4;
    int row0 = blockIdx.y * 64;
    int col0 = blockIdx.x * 64;
    float acc[4][4] = {};

    for (int kk0 = 0; kk0 < DKsz; kk0 += 32) {
        int c = tid & 31, r = tid >> 5;
        #pragma unroll
        for (int i = 0; i < 8; i++)
            As[r + i*8][c] = Ap[(size_t)(row0 + r + i*8) * Dsz + kk0 + c];
        #pragma unroll
        for (int i = 0; i < 8; i++)
            Bs[r + i*8][c] = Bp[(size_t)(col0 + r + i*8) * Dsz + kk0 + c];
        __syncthreads();
        #pragma unroll
        for (int kk = 0; kk < 32; kk++) {
            float a[4], bb[4];
            #pragma unroll
            for (int i = 0; i < 4; i++) a[i] = As[ty*4 + i][kk];
            #pragma unroll
            for (int j = 0; j < 4; j++) bb[j] = Bs[tx*4 + j][kk];
            #pragma unroll
            for (int i = 0; i < 4; i++)
                #pragma unroll
                for (int j = 0; j < 4; j++)
                    acc[i][j] += a[i] * bb[j];
        }
        __syncthreads();
    }
    #pragma unroll
    for (int i = 0; i < 4; i++) {
        int row = row0 + ty*4 + i;
        #pragma unroll
        for (int j = 0; j < 4; j++)
            Cp[(size_t)row * Lsz + col0 + tx*4 + j] = acc[i][j] * SCALE;
    }
}

// ---------------- block reductions ----------------
__device__ __forceinline__ float blk_max(float v)
{
    __shared__ float sh[8];
    #pragma unroll
    for (int o = 16; o; o >>= 1) v = fmaxf(v, __shfl_xor_sync(0xffffffffu, v, o));
    if ((threadIdx.x & 31) == 0) sh[threadIdx.x >> 5] = v;
    __syncthreads();
    float r = sh[0];
    #pragma unroll
    for (int i = 1; i < 8; i++) r = fmaxf(r, sh[i]);
    __syncthreads();
    return r;
}

__device__ __forceinline__ float blk_sum(float v)
{
    __shared__ float sh[8];
    #pragma unroll
    for (int o = 16; o; o >>= 1) v += __shfl_xor_sync(0xffffffffu, v, o);
    if ((threadIdx.x & 31) == 0) sh[threadIdx.x >> 5] = v;
    __syncthreads();
    float r = 0.f;
    #pragma unroll
    for (int i = 0; i < 8; i++) r += sh[i];
    __syncthreads();
    return r;
}

// ---------------- fused softmax -> reweight -> softmax (row-wise, in place on g_S) ----------------
__global__ void softmax_kernel()
{
    int rid = blockIdx.x;          // over B*H*L rows
    int q = rid & (Lsz - 1);
    int z = rid >> 10;             // b*H + h
    int b = z >> 3;
    float* Srow = g_S + (size_t)z * Lsz * Lsz + (size_t)q * Lsz;
    const float* Erow = g_EM + ((size_t)b * Lsz + q) * Lsz;
    float g = g_G[b * Lsz + q];
    int t = threadIdx.x;           // 256 threads, 4 elems each

    float x[4];
    #pragma unroll
    for (int i = 0; i < 4; i++) x[i] = Srow[t + i*256];

    float mx = fmaxf(fmaxf(x[0], x[1]), fmaxf(x[2], x[3]));
    mx = blk_max(mx);

    float p[4], s = 0.f;
    #pragma unroll
    for (int i = 0; i < 4; i++) { p[i] = expf(x[i] - mx); s += p[i]; }
    float Z = blk_sum(s);
    float invZ = 1.0f / Z;

    float c[4];
    #pragma unroll
    for (int i = 0; i < 4; i++) {
        float w = g + (1.0f - g) * Erow[t + i*256];
        c[i] = p[i] * invZ * w;
    }

    float mx2 = fmaxf(fmaxf(c[0], c[1]), fmaxf(c[2], c[3]));
    mx2 = blk_max(mx2);

    float e2[4], s2 = 0.f;
    #pragma unroll
    for (int i = 0; i < 4; i++) { e2[i] = expf(c[i] - mx2); s2 += e2[i]; }
    float Z2 = blk_sum(s2);
    float invZ2 = 1.0f / Z2;

    #pragma unroll
    for (int i = 0; i < 4; i++) Srow[t + i*256] = e2[i] * invZ2;
}

// ---------------- ctx GEMM (NN, per (b,h)): CTX = attn(1024x1024) @ Vh(1024x64) ----------------
__global__ void ctx_gemm_kernel()
{
    int z = blockIdx.z;
    int b = z >> 3, h = z & 7;
    const float* Ap = g_S + (size_t)z * Lsz * Lsz;
    const float* Bp = g_V + (size_t)b * Lsz * Dsz + h * DKsz;
    float* Cp = g_CTX + (size_t)b * Lsz * Dsz + h * DKsz;

    __shared__ float As[64][33];
    __shared__ float Bs[32][65];
    int tid = threadIdx.x;
    int tx = tid & 15, ty = tid >> 4;
    int row0 = blockIdx.y * 64;
    float acc[4][4] = {};

    for (int kk0 = 0; kk0 < Lsz; kk0 += 32) {
        {
            int c = tid & 31, r = tid >> 5;
            #pragma unroll
            for (int i = 0; i < 8; i++)
                As[r + i*8][c] = Ap[(size_t)(row0 + r + i*8) * Lsz + kk0 + c];
        }
        {
            int c = tid & 63, r = tid >> 6;
            #pragma unroll
            for (int i = 0; i < 8; i++)
                Bs[r + i*4][c] = Bp[(size_t)(kk0 + r + i*4) * Dsz + c];
        }
        __syncthreads();
        #pragma unroll
        for (int kk = 0; kk < 32; kk++) {
            float a[4], bb[4];
            #pragma unroll
            for (int i = 0; i < 4; i++) a[i] = As[ty*4 + i][kk];
            #pragma unroll
            for (int j = 0; j < 4; j++) bb[j] = Bs[kk][tx*4 + j];
            #pragma unroll
            for (int i = 0; i < 4; i++)
                #pragma unroll
                for (int j = 0; j < 4; j++)
                    acc[i][j] += a[i] * bb[j];
        }
        __syncthreads();
    }
    #pragma unroll
    for (int i = 0; i < 4; i++) {
        int row = row0 + ty*4 + i;
        #pragma unroll
        for (int j = 0; j < 4; j++)
            Cp[(size_t)row * Dsz + tx*4 + j] = acc[i][j];
    }
}

// ---------------- gate: g = sigmoid(query @ gate_w + gate_b), one warp per row ----------------
__global__ void gate_kernel(const float* __restrict__ query,
                            const float* __restrict__ gw,
                            const float* __restrict__ gb)
{
    int warp = (blockIdx.x * blockDim.x + threadIdx.x) >> 5;
    int lane = threadIdx.x & 31;
    if (warp >= Bsz * Lsz) return;
    const float* row = query + (size_t)warp * Dsz;
    float s = 0.f;
    for (int d = lane; d < Dsz; d += 32) s += row[d] * gw[d];
    #pragma unroll
    for (int o = 16; o; o >>= 1) s += __shfl_xor_sync(0xffffffffu, s, o);
    if (lane == 0) g_G[warp] = 1.0f / (1.0f + expf(-(s + gb[0])));
}

// ---------------- launch ----------------
extern "C" void kernel_launch(void* const* d_in, const int* in_sizes, int n_in,
                              void* d_out, int out_size)
{
    const float* query   = (const float*)d_in[0];
    const float* key     = (const float*)d_in[1];
    const float* value   = (const float*)d_in[2];
    const float* wq_w    = (const float*)d_in[3];
    const float* wq_b    = (const float*)d_in[4];
    const float* wk_w    = (const float*)d_in[5];
    const float* wk_b    = (const float*)d_in[6];
    const float* wv_w    = (const float*)d_in[7];
    const float* wv_b    = (const float*)d_in[8];
    const float* dense_w = (const float*)d_in[9];
    const float* dense_b = (const float*)d_in[10];
    const float* gate_w  = (const float*)d_in[11];
    const float* gate_b  = (const float*)d_in[12];
    const float* mp_wq_w = (const float*)d_in[13];
    const float* mp_wq_b = (const float*)d_in[14];
    const float* mp_wk_w = (const float*)d_in[15];
    const float* mp_wk_b = (const float*)d_in[16];

    float* out   = (float*)d_out;
    float* m_out = out + (size_t)Bsz * Lsz * Dsz;

    float *pQ, *pK, *pV, *pQP, *pKP, *pCTX;
    cudaGetSymbolAddress((void**)&pQ,   g_Q);
    cudaGetSymbolAddress((void**)&pK,   g_K);
    cudaGetSymbolAddress((void**)&pV,   g_V);
    cudaGetSymbolAddress((void**)&pQP,  g_QP);
    cudaGetSymbolAddress((void**)&pKP,  g_KP);
    cudaGetSymbolAddress((void**)&pCTX, g_CTX);

    const int M = Bsz * Lsz;     // 4096
    dim3 t256(256);
    dim3 gproj(Dsz / 64, M / 64);  // (8, 64)

    gemm_nn_bias_kernel<<<gproj, t256>>>(query, wq_w, wq_b, pQ,  M, Dsz, Dsz);
    gemm_nn_bias_kernel<<<gproj, t256>>>(key,   wk_w, wk_b, pK,  M, Dsz, Dsz);
    gemm_nn_bias_kernel<<<gproj, t256>>>(value, wv_w, wv_b, pV,  M, Dsz, Dsz);
    gemm_nn_bias_kernel<<<gproj, t256>>>(query, mp_wq_w, mp_wq_b, pQP, M, Dsz, Dsz);
    gemm_nn_bias_kernel<<<gproj, t256>>>(key,   mp_wk_w, mp_wk_b, pKP, M, Dsz, Dsz);

    gate_kernel<<<(Bsz * Lsz * 32) / 256, 256>>>(query, gate_w, gate_b);

    m_gemm_kernel<<<dim3(16, 16, Bsz), t256>>>(m_out);

    score_gemm_kernel<<<dim3(16, 16, Bsz * Hsz), t256>>>();

    softmax_kernel<<<Bsz * Hsz * Lsz, 256>>>();

    ctx_gemm_kernel<<<dim3(1, 16, Bsz * Hsz), t256>>>();

    gemm_nn_bias_kernel<<<gproj, t256>>>(pCTX, dense_w, dense_b, out, M, Dsz, Dsz);
}

// round 2
// speedup vs baseline: 2.4741x; 2.4741x over previous
#include <cuda_runtime.h>
#include <math.h>

#define Bsz 4
#define Lsz 1024
#define Dsz 512
#define Hsz 8
#define DKsz 64

// ---------------- scratch (static device globals; no allocation) ----------------
__device__ float g_Q[Bsz*Lsz*Dsz];
__device__ float g_K[Bsz*Lsz*Dsz];
__device__ float g_V[Bsz*Lsz*Dsz];
__device__ float g_QP[Bsz*Lsz*Dsz];
__device__ float g_KP[Bsz*Lsz*Dsz];
__device__ float g_EM[Bsz*Lsz*Lsz];
__device__ float g_G[Bsz*Lsz];
__device__ float g_S[(size_t)Bsz*Hsz*Lsz*Lsz];
__device__ float g_CTX[Bsz*Lsz*Dsz];

// ---------------- tf32 helpers ----------------
__device__ __forceinline__ unsigned f2tf(float f) {
    unsigned u;
    asm("cvt.rna.tf32.f32 %0, %1;" : "=r"(u) : "f"(f));
    return u;
}

__device__ __forceinline__ void mma_tf32(float c[4], const unsigned a[4], const unsigned b[2]) {
    asm volatile(
        "mma.sync.aligned.m16n8k8.row.col.f32.tf32.tf32.f32 "
        "{%0,%1,%2,%3}, {%4,%5,%6,%7}, {%8,%9}, {%0,%1,%2,%3};"
        : "+f"(c[0]), "+f"(c[1]), "+f"(c[2]), "+f"(c[3])
        : "r"(a[0]), "r"(a[1]), "r"(a[2]), "r"(a[3]), "r"(b[0]), "r"(b[1]));
}

// ---------------- tf32 GEMM core ----------------
// Block: 256 threads = 8 warps (4 in M x 2 in N).
// A: row-major MxK (ptr pre-offset to block row0, k=0), lda in floats.
// B: if BT (NT gemm): row-major NxK, ptr pre-offset to block col0 row;
//    else (NN gemm): row-major KxN, ptr pre-offset to (0, col0).
// acc[MT][NT][4] fp32 fragments.
template<int BM, int BN, bool BT, int MT, int NT>
__device__ __forceinline__ void gemm_core(
    const float* __restrict__ A, int lda,
    const float* __restrict__ B, int ldb,
    int K, float (&acc)[MT][NT][4])
{
    constexpr int BK = 16;
    // A and NT-B: [rows][BK+4] layout -> stride 20 words (conflict-free frag LDS)
    __shared__ unsigned As[BM][BK + 4];
    __shared__ unsigned Bs[BT ? BN : BK][BT ? (BK + 4) : (BN + 8)];

    const int tid = threadIdx.x;
    const int lane = tid & 31;
    const int wid = tid >> 5;
    const int wm0 = (wid & 3) * (BM / 4);
    const int wn0 = (wid >> 2) * (BN / 2);

    constexpr int A_F4 = BM * BK / 4;          // float4s per A tile
    constexpr int ALD = A_F4 / 256;
    constexpr int B_F4 = BT ? (BN * BK / 4) : (BK * BN / 4);
    constexpr int BLD = B_F4 / 256;

    float4 bufA[ALD], bufB[BLD];

    auto loadA = [&](int k0) {
        #pragma unroll
        for (int i = 0; i < ALD; i++) {
            int idx = tid + i * 256;
            int row = idx >> 2, kq = idx & 3;
            bufA[i] = *(const float4*)(A + (size_t)row * lda + k0 + kq * 4);
        }
    };
    auto loadB = [&](int k0) {
        #pragma unroll
        for (int i = 0; i < BLD; i++) {
            int idx = tid + i * 256;
            if constexpr (BT) {
                int row = idx >> 2, kq = idx & 3;   // row = n
                bufB[i] = *(const float4*)(B + (size_t)row * ldb + k0 + kq * 4);
            } else {
                int k = idx / (BN / 4), nq = idx % (BN / 4);
                bufB[i] = *(const float4*)(B + (size_t)(k0 + k) * ldb + nq * 4);
            }
        }
    };
    auto storeA = [&]() {
        #pragma unroll
        for (int i = 0; i < ALD; i++) {
            int idx = tid + i * 256;
            int row = idx >> 2, kq = idx & 3;
            uint4 v = make_uint4(f2tf(bufA[i].x), f2tf(bufA[i].y),
                                 f2tf(bufA[i].z), f2tf(bufA[i].w));
            *(uint4*)&As[row][kq * 4] = v;
        }
    };
    auto storeB = [&]() {
        #pragma unroll
        for (int i = 0; i < BLD; i++) {
            int idx = tid + i * 256;
            uint4 v = make_uint4(f2tf(bufB[i].x), f2tf(bufB[i].y),
                                 f2tf(bufB[i].z), f2tf(bufB[i].w));
            if constexpr (BT) {
                int row = idx >> 2, kq = idx & 3;
                *(uint4*)&Bs[row][kq * 4] = v;
            } else {
                int k = idx / (BN / 4), nq = idx % (BN / 4);
                *(uint4*)&Bs[k][nq * 4] = v;
            }
        }
    };

    const int nIter = K / BK;
    loadA(0); loadB(0);
    storeA(); storeB();
    __syncthreads();

    for (int it = 0; it < nIter; it++) {
        if (it + 1 < nIter) { loadA((it + 1) * BK); loadB((it + 1) * BK); }

        #pragma unroll
        for (int ks = 0; ks < 2; ks++) {
            unsigned af[MT][4];
            unsigned bf[NT][2];
            int kk = ks * 8 + (lane & 3);
            #pragma unroll
            for (int mt = 0; mt < MT; mt++) {
                int row = wm0 + mt * 16 + (lane >> 2);
                af[mt][0] = As[row][kk];
                af[mt][1] = As[row + 8][kk];
                af[mt][2] = As[row][kk + 4];
                af[mt][3] = As[row + 8][kk + 4];
            }
            #pragma unroll
            for (int nt = 0; nt < NT; nt++) {
                int n = wn0 + nt * 8 + (lane >> 2);
                if constexpr (BT) {
                    bf[nt][0] = Bs[n][kk];
                    bf[nt][1] = Bs[n][kk + 4];
                } else {
                    bf[nt][0] = Bs[kk][n];
                    bf[nt][1] = Bs[kk + 4][n];
                }
            }
            #pragma unroll
            for (int mt = 0; mt < MT; mt++)
                #pragma unroll
                for (int nt = 0; nt < NT; nt++)
                    mma_tf32(acc[mt][nt], af[mt], bf[nt]);
        }
        __syncthreads();
        if (it + 1 < nIter) { storeA(); storeB(); __syncthreads(); }
    }
}

// ---------------- projections / dense: C = A @ W + bias (NN) ----------------
__global__ void __launch_bounds__(256) proj_gemm_kernel(
    const float* __restrict__ A, const float* __restrict__ W,
    const float* __restrict__ bias, float* __restrict__ C, int N, int K)
{
    float acc[2][8][4] = {};
    const float* Ab = A + (size_t)blockIdx.y * 128 * K;
    const float* Bb = W + blockIdx.x * 128;
    gemm_core<128, 128, false, 2, 8>(Ab, K, Bb, N, K, acc);

    int lane = threadIdx.x & 31, wid = threadIdx.x >> 5;
    int rowBase = blockIdx.y * 128 + (wid & 3) * 32 + (lane >> 2);
    int colBase = blockIdx.x * 128 + (wid >> 2) * 64 + 2 * (lane & 3);
    #pragma unroll
    for (int mt = 0; mt < 2; mt++)
        #pragma unroll
        for (int nt = 0; nt < 8; nt++) {
            int row = rowBase + mt * 16;
            int col = colBase + nt * 8;
            float b0 = bias[col], b1 = bias[col + 1];
            *(float2*)&C[(size_t)row * N + col] =
                make_float2(acc[mt][nt][0] + b0, acc[mt][nt][1] + b1);
            *(float2*)&C[(size_t)(row + 8) * N + col] =
                make_float2(acc[mt][nt][2] + b0, acc[mt][nt][3] + b1);
        }
}

// ---------------- m GEMM (NT per batch): m = sigmoid(QP @ KP^T / sqrt(D)), EM = exp(1-m) ----
__global__ void __launch_bounds__(256) m_gemm_kernel(float* __restrict__ m_out)
{
    const float SCALE = 0.04419417382415922f; // 1/sqrt(512)
    int zb = blockIdx.z;
    float acc[2][8][4] = {};
    const float* Ab = g_QP + (size_t)zb * Lsz * Dsz + (size_t)blockIdx.y * 128 * Dsz;
    const float* Bb = g_KP + (size_t)zb * Lsz * Dsz + (size_t)blockIdx.x * 128 * Dsz;
    gemm_core<128, 128, true, 2, 8>(Ab, Dsz, Bb, Dsz, Dsz, acc);

    float* Mo = m_out + (size_t)zb * Lsz * Lsz;
    float* Eo = g_EM + (size_t)zb * Lsz * Lsz;
    int lane = threadIdx.x & 31, wid = threadIdx.x >> 5;
    int rowBase = blockIdx.y * 128 + (wid & 3) * 32 + (lane >> 2);
    int colBase = blockIdx.x * 128 + (wid >> 2) * 64 + 2 * (lane & 3);
    #pragma unroll
    for (int mt = 0; mt < 2; mt++)
        #pragma unroll
        for (int nt = 0; nt < 8; nt++) {
            int row = rowBase + mt * 16;
            int col = colBase + nt * 8;
            #pragma unroll
            for (int h = 0; h < 2; h++) {
                int r = row + h * 8;
                float s0 = 1.0f / (1.0f + __expf(-acc[mt][nt][2*h] * SCALE));
                float s1 = 1.0f / (1.0f + __expf(-acc[mt][nt][2*h+1] * SCALE));
                *(float2*)&Mo[(size_t)r * Lsz + col] = make_float2(s0, s1);
                *(float2*)&Eo[(size_t)r * Lsz + col] =
                    make_float2(__expf(1.0f - s0), __expf(1.0f - s1));
            }
        }
}

// ---------------- score GEMM (NT per (b,h)): S = Qh @ Kh^T / sqrt(DK) ----------------
__global__ void __launch_bounds__(256) score_gemm_kernel()
{
    const float SCALE = 0.125f;
    int z = blockIdx.z;
    int b = z >> 3, h = z & 7;
    float acc[2][8][4] = {};
    const float* Ab = g_Q + (size_t)b * Lsz * Dsz + h * DKsz + (size_t)blockIdx.y * 128 * Dsz;
    const float* Bb = g_K + (size_t)b * Lsz * Dsz + h * DKsz + (size_t)blockIdx.x * 128 * Dsz;
    gemm_core<128, 128, true, 2, 8>(Ab, Dsz, Bb, Dsz, DKsz, acc);

    float* Cp = g_S + (size_t)z * Lsz * Lsz;
    int lane = threadIdx.x & 31, wid = threadIdx.x >> 5;
    int rowBase = blockIdx.y * 128 + (wid & 3) * 32 + (lane >> 2);
    int colBase = blockIdx.x * 128 + (wid >> 2) * 64 + 2 * (lane & 3);
    #pragma unroll
    for (int mt = 0; mt < 2; mt++)
        #pragma unroll
        for (int nt = 0; nt < 8; nt++) {
            int row = rowBase + mt * 16;
            int col = colBase + nt * 8;
            *(float2*)&Cp[(size_t)row * Lsz + col] =
                make_float2(acc[mt][nt][0] * SCALE, acc[mt][nt][1] * SCALE);
            *(float2*)&Cp[(size_t)(row + 8) * Lsz + col] =
                make_float2(acc[mt][nt][2] * SCALE, acc[mt][nt][3] * SCALE);
        }
}

// ---------------- ctx GEMM (NN per (b,h)): CTX = attn @ Vh ----------------
__global__ void __launch_bounds__(256) ctx_gemm_kernel()
{
    int z = blockIdx.z;
    int b = z >> 3, h = z & 7;
    float acc[2][4][4] = {};
    const float* Ab = g_S + (size_t)z * Lsz * Lsz + (size_t)blockIdx.y * 128 * Lsz;
    const float* Bb = g_V + (size_t)b * Lsz * Dsz + h * DKsz;
    gemm_core<128, 64, false, 2, 4>(Ab, Lsz, Bb, Dsz, Lsz, acc);

    float* Cp = g_CTX + (size_t)b * Lsz * Dsz + h * DKsz;
    int lane = threadIdx.x & 31, wid = threadIdx.x >> 5;
    int rowBase = blockIdx.y * 128 + (wid & 3) * 32 + (lane >> 2);
    int colBase = (wid >> 2) * 32 + 2 * (lane & 3);
    #pragma unroll
    for (int mt = 0; mt < 2; mt++)
        #pragma unroll
        for (int nt = 0; nt < 4; nt++) {
            int row = rowBase + mt * 16;
            int col = colBase + nt * 8;
            *(float2*)&Cp[(size_t)row * Dsz + col] =
                make_float2(acc[mt][nt][0], acc[mt][nt][1]);
            *(float2*)&Cp[(size_t)(row + 8) * Dsz + col] =
                make_float2(acc[mt][nt][2], acc[mt][nt][3]);
        }
}

// ---------------- block reductions ----------------
__device__ __forceinline__ float blk_max(float v)
{
    __shared__ float sh[8];
    #pragma unroll
    for (int o = 16; o; o >>= 1) v = fmaxf(v, __shfl_xor_sync(0xffffffffu, v, o));
    if ((threadIdx.x & 31) == 0) sh[threadIdx.x >> 5] = v;
    __syncthreads();
    float r = sh[0];
    #pragma unroll
    for (int i = 1; i < 8; i++) r = fmaxf(r, sh[i]);
    __syncthreads();
    return r;
}

__device__ __forceinline__ float blk_sum(float v)
{
    __shared__ float sh[8];
    #pragma unroll
    for (int o = 16; o; o >>= 1) v += __shfl_xor_sync(0xffffffffu, v, o);
    if ((threadIdx.x & 31) == 0) sh[threadIdx.x >> 5] = v;
    __syncthreads();
    float r = 0.f;
    #pragma unroll
    for (int i = 0; i < 8; i++) r += sh[i];
    __syncthreads();
    return r;
}

// ---------------- fused softmax -> reweight -> softmax (row-wise, in place on g_S) ----------------
__global__ void softmax_kernel()
{
    int rid = blockIdx.x;
    int q = rid & (Lsz - 1);
    int z = rid >> 10;
    int b = z >> 3;
    float* Srow = g_S + (size_t)z * Lsz * Lsz + (size_t)q * Lsz;
    const float* Erow = g_EM + ((size_t)b * Lsz + q) * Lsz;
    float g = g_G[b * Lsz + q];
    int t = threadIdx.x;

    float x[4];
    #pragma unroll
    for (int i = 0; i < 4; i++) x[i] = Srow[t + i * 256];

    float mx = fmaxf(fmaxf(x[0], x[1]), fmaxf(x[2], x[3]));
    mx = blk_max(mx);

    float p[4], s = 0.f;
    #pragma unroll
    for (int i = 0; i < 4; i++) { p[i] = __expf(x[i] - mx); s += p[i]; }
    float Z = blk_sum(s);
    float invZ = 1.0f / Z;

    float c[4];
    #pragma unroll
    for (int i = 0; i < 4; i++) {
        float w = g + (1.0f - g) * Erow[t + i * 256];
        c[i] = p[i] * invZ * w;
    }

    float mx2 = fmaxf(fmaxf(c[0], c[1]), fmaxf(c[2], c[3]));
    mx2 = blk_max(mx2);

    float e2[4], s2 = 0.f;
    #pragma unroll
    for (int i = 0; i < 4; i++) { e2[i] = __expf(c[i] - mx2); s2 += e2[i]; }
    float Z2 = blk_sum(s2);
    float invZ2 = 1.0f / Z2;

    #pragma unroll
    for (int i = 0; i < 4; i++) Srow[t + i * 256] = e2[i] * invZ2;
}

// ---------------- gate ----------------
__global__ void gate_kernel(const float* __restrict__ query,
                            const float* __restrict__ gw,
                            const float* __restrict__ gb)
{
    int warp = (blockIdx.x * blockDim.x + threadIdx.x) >> 5;
    int lane = threadIdx.x & 31;
    if (warp >= Bsz * Lsz) return;
    const float* row = query + (size_t)warp * Dsz;
    float s = 0.f;
    for (int d = lane; d < Dsz; d += 32) s += row[d] * gw[d];
    #pragma unroll
    for (int o = 16; o; o >>= 1) s += __shfl_xor_sync(0xffffffffu, s, o);
    if (lane == 0) g_G[warp] = 1.0f / (1.0f + __expf(-(s + gb[0])));
}

// ---------------- launch ----------------
extern "C" void kernel_launch(void* const* d_in, const int* in_sizes, int n_in,
                              void* d_out, int out_size)
{
    const float* query   = (const float*)d_in[0];
    const float* key     = (const float*)d_in[1];
    const float* value   = (const float*)d_in[2];
    const float* wq_w    = (const float*)d_in[3];
    const float* wq_b    = (const float*)d_in[4];
    const float* wk_w    = (const float*)d_in[5];
    const float* wk_b    = (const float*)d_in[6];
    const float* wv_w    = (const float*)d_in[7];
    const float* wv_b    = (const float*)d_in[8];
    const float* dense_w = (const float*)d_in[9];
    const float* dense_b = (const float*)d_in[10];
    const float* gate_w  = (const float*)d_in[11];
    const float* gate_b  = (const float*)d_in[12];
    const float* mp_wq_w = (const float*)d_in[13];
    const float* mp_wq_b = (const float*)d_in[14];
    const float* mp_wk_w = (const float*)d_in[15];
    const float* mp_wk_b = (const float*)d_in[16];

    float* out   = (float*)d_out;
    float* m_out = out + (size_t)Bsz * Lsz * Dsz;

    float *pQ, *pK, *pV, *pQP, *pKP, *pCTX;
    cudaGetSymbolAddress((void**)&pQ,   g_Q);
    cudaGetSymbolAddress((void**)&pK,   g_K);
    cudaGetSymbolAddress((void**)&pV,   g_V);
    cudaGetSymbolAddress((void**)&pQP,  g_QP);
    cudaGetSymbolAddress((void**)&pKP,  g_KP);
    cudaGetSymbolAddress((void**)&pCTX, g_CTX);

    dim3 t256(256);
    dim3 gproj(Dsz / 128, (Bsz * Lsz) / 128);   // (4, 32)

    proj_gemm_kernel<<<gproj, t256>>>(query, wq_w, wq_b, pQ,  Dsz, Dsz);
    proj_gemm_kernel<<<gproj, t256>>>(key,   wk_w, wk_b, pK,  Dsz, Dsz);
    proj_gemm_kernel<<<gproj, t256>>>(value, wv_w, wv_b, pV,  Dsz, Dsz);
    proj_gemm_kernel<<<gproj, t256>>>(query, mp_wq_w, mp_wq_b, pQP, Dsz, Dsz);
    proj_gemm_kernel<<<gproj, t256>>>(key,   mp_wk_w, mp_wk_b, pKP, Dsz, Dsz);

    gate_kernel<<<(Bsz * Lsz * 32) / 256, 256>>>(query, gate_w, gate_b);

    m_gemm_kernel<<<dim3(8, 8, Bsz), t256>>>(m_out);

    score_gemm_kernel<<<dim3(8, 8, Bsz * Hsz), t256>>>();

    softmax_kernel<<<Bsz * Hsz * Lsz, 256>>>();

    ctx_gemm_kernel<<<dim3(1, 8, Bsz * Hsz), t256>>>();

    proj_gemm_kernel<<<gproj, t256>>>(pCTX, dense_w, dense_b, out, Dsz, Dsz);
}

// round 3
// speedup vs baseline: 3.1321x; 1.2659x over previous
#include <cuda_runtime.h>
#include <math.h>

#define Bsz 4
#define Lsz 1024
#define Dsz 512
#define Hsz 8
#define DKsz 64

// ---------------- scratch (static device globals; no allocation) ----------------
__device__ float g_Q[Bsz*Lsz*Dsz];
__device__ float g_K[Bsz*Lsz*Dsz];
__device__ float g_V[Bsz*Lsz*Dsz];
__device__ float g_QP[Bsz*Lsz*Dsz];
__device__ float g_KP[Bsz*Lsz*Dsz];
__device__ float g_EM[Bsz*Lsz*Lsz];
__device__ float g_G[Bsz*Lsz];
__device__ float g_S[(size_t)Bsz*Hsz*Lsz*Lsz];
__device__ float g_CTX[Bsz*Lsz*Dsz];

// ---------------- helpers ----------------
__device__ __forceinline__ unsigned f2tf(float f) {
    unsigned u;
    asm("cvt.rna.tf32.f32 %0, %1;" : "=r"(u) : "f"(f));
    return u;
}

__device__ __forceinline__ void mma_tf32(float c[4], const unsigned a[4], const unsigned b[2]) {
    asm volatile(
        "mma.sync.aligned.m16n8k8.row.col.f32.tf32.tf32.f32 "
        "{%0,%1,%2,%3}, {%4,%5,%6,%7}, {%8,%9}, {%0,%1,%2,%3};"
        : "+f"(c[0]), "+f"(c[1]), "+f"(c[2]), "+f"(c[3])
        : "r"(a[0]), "r"(a[1]), "r"(a[2]), "r"(a[3]), "r"(b[0]), "r"(b[1]));
}

__device__ __forceinline__ void cp_async16(void* smem, const void* gmem) {
    unsigned saddr = (unsigned)__cvta_generic_to_shared(smem);
    asm volatile("cp.async.cg.shared.global [%0], [%1], 16;" :: "r"(saddr), "l"(gmem));
}
__device__ __forceinline__ void cp_commit() { asm volatile("cp.async.commit_group;"); }
template<int N>
__device__ __forceinline__ void cp_wait() { asm volatile("cp.async.wait_group %0;" :: "n"(N)); }

// ---------------- tf32 GEMM core, 2-stage cp.async pipeline ----------------
// Block: 256 threads = 8 warps (4 in M x 2 in N).
// A: row-major MxK, ptr pre-offset to block row0 (k=0), lda in floats.
// B: if BT (NT): row-major NxK, ptr pre-offset to block col0 row;
//    else (NN): row-major KxN, ptr pre-offset to (0, col0).
template<int BM, int BN, bool BT, int MT, int NT>
__device__ __forceinline__ void gemm_core(
    const float* __restrict__ A, int lda,
    const float* __restrict__ B, int ldb,
    int K, float (&acc)[MT][NT][4])
{
    constexpr int BK = 16;
    __shared__ float As[2][BM][BK + 4];
    __shared__ float Bs[2][BT ? BN : BK][BT ? (BK + 4) : (BN + 8)];

    const int tid = threadIdx.x;
    const int lane = tid & 31;
    const int wid = tid >> 5;
    const int wm0 = (wid & 3) * (BM / 4);
    const int wn0 = (wid >> 2) * (BN / 2);

    constexpr int ALD = (BM * BK / 4) / 256;
    constexpr int BLD = (BT ? (BN * BK / 4) : (BK * BN / 4)) / 256;

    auto prefetch = [&](int k0, int s) {
        #pragma unroll
        for (int i = 0; i < ALD; i++) {
            int idx = tid + i * 256;
            int row = idx >> 2, kq = idx & 3;
            cp_async16(&As[s][row][kq * 4], A + (size_t)row * lda + k0 + kq * 4);
        }
        #pragma unroll
        for (int i = 0; i < BLD; i++) {
            int idx = tid + i * 256;
            if constexpr (BT) {
                int row = idx >> 2, kq = idx & 3;
                cp_async16(&Bs[s][row][kq * 4], B + (size_t)row * ldb + k0 + kq * 4);
            } else {
                int k = idx / (BN / 4), nq = idx % (BN / 4);
                cp_async16(&Bs[s][k][nq * 4], B + (size_t)(k0 + k) * ldb + nq * 4);
            }
        }
        cp_commit();
    };

    const int nIter = K / BK;
    prefetch(0, 0);

    for (int it = 0; it < nIter; it++) {
        const int cur = it & 1;
        if (it + 1 < nIter) { prefetch((it + 1) * BK, cur ^ 1); cp_wait<1>(); }
        else                { cp_wait<0>(); }
        __syncthreads();

        #pragma unroll
        for (int ks = 0; ks < 2; ks++) {
            unsigned af[MT][4];
            unsigned bf[NT][2];
            const int kk = ks * 8 + (lane & 3);
            #pragma unroll
            for (int mt = 0; mt < MT; mt++) {
                int row = wm0 + mt * 16 + (lane >> 2);
                af[mt][0] = f2tf(As[cur][row][kk]);
                af[mt][1] = f2tf(As[cur][row + 8][kk]);
                af[mt][2] = f2tf(As[cur][row][kk + 4]);
                af[mt][3] = f2tf(As[cur][row + 8][kk + 4]);
            }
            #pragma unroll
            for (int nt = 0; nt < NT; nt++) {
                int n = wn0 + nt * 8 + (lane >> 2);
                if constexpr (BT) {
                    bf[nt][0] = f2tf(Bs[cur][n][kk]);
                    bf[nt][1] = f2tf(Bs[cur][n][kk + 4]);
                } else {
                    bf[nt][0] = f2tf(Bs[cur][kk][n]);
                    bf[nt][1] = f2tf(Bs[cur][kk + 4][n]);
                }
            }
            #pragma unroll
            for (int mt = 0; mt < MT; mt++)
                #pragma unroll
                for (int nt = 0; nt < NT; nt++)
                    mma_tf32(acc[mt][nt], af[mt], bf[nt]);
        }
        __syncthreads();
    }
}

// ---------------- batched projections / dense: C[z] = A[z] @ W[z] + bias[z] (NN) ----------------
struct ProjArgs {
    const float* A[5];
    const float* W[5];
    const float* bias[5];
    float* C[5];
};

__global__ void __launch_bounds__(256, 2) proj_gemm_kernel(ProjArgs args, int N, int K)
{
    const int z = blockIdx.z;
    float acc[2][8][4] = {};
    const float* Ab = args.A[z] + (size_t)blockIdx.y * 128 * K;
    const float* Bb = args.W[z] + blockIdx.x * 128;
    gemm_core<128, 128, false, 2, 8>(Ab, K, Bb, N, K, acc);

    const float* bias = args.bias[z];
    float* C = args.C[z];
    int lane = threadIdx.x & 31, wid = threadIdx.x >> 5;
    int rowBase = blockIdx.y * 128 + (wid & 3) * 32 + (lane >> 2);
    int colBase = blockIdx.x * 128 + (wid >> 2) * 64 + 2 * (lane & 3);
    #pragma unroll
    for (int mt = 0; mt < 2; mt++)
        #pragma unroll
        for (int nt = 0; nt < 8; nt++) {
            int row = rowBase + mt * 16;
            int col = colBase + nt * 8;
            float b0 = bias[col], b1 = bias[col + 1];
            *(float2*)&C[(size_t)row * N + col] =
                make_float2(acc[mt][nt][0] + b0, acc[mt][nt][1] + b1);
            *(float2*)&C[(size_t)(row + 8) * N + col] =
                make_float2(acc[mt][nt][2] + b0, acc[mt][nt][3] + b1);
        }
}

// ---------------- m GEMM (NT per batch): m = sigmoid(QP @ KP^T / sqrt(D)), EM = exp(1-m) ----
__global__ void __launch_bounds__(256, 2) m_gemm_kernel(float* __restrict__ m_out)
{
    const float SCALE = 0.04419417382415922f; // 1/sqrt(512)
    int zb = blockIdx.z;
    float acc[2][8][4] = {};
    const float* Ab = g_QP + (size_t)zb * Lsz * Dsz + (size_t)blockIdx.y * 128 * Dsz;
    const float* Bb = g_KP + (size_t)zb * Lsz * Dsz + (size_t)blockIdx.x * 128 * Dsz;
    gemm_core<128, 128, true, 2, 8>(Ab, Dsz, Bb, Dsz, Dsz, acc);

    float* Mo = m_out + (size_t)zb * Lsz * Lsz;
    float* Eo = g_EM + (size_t)zb * Lsz * Lsz;
    int lane = threadIdx.x & 31, wid = threadIdx.x >> 5;
    int rowBase = blockIdx.y * 128 + (wid & 3) * 32 + (lane >> 2);
    int colBase = blockIdx.x * 128 + (wid >> 2) * 64 + 2 * (lane & 3);
    #pragma unroll
    for (int mt = 0; mt < 2; mt++)
        #pragma unroll
        for (int nt = 0; nt < 8; nt++) {
            int row = rowBase + mt * 16;
            int col = colBase + nt * 8;
            #pragma unroll
            for (int h = 0; h < 2; h++) {
                int r = row + h * 8;
                float s0 = 1.0f / (1.0f + __expf(-acc[mt][nt][2*h] * SCALE));
                float s1 = 1.0f / (1.0f + __expf(-acc[mt][nt][2*h+1] * SCALE));
                *(float2*)&Mo[(size_t)r * Lsz + col] = make_float2(s0, s1);
                *(float2*)&Eo[(size_t)r * Lsz + col] =
                    make_float2(__expf(1.0f - s0), __expf(1.0f - s1));
            }
        }
}

// ---------------- score GEMM (NT per (b,h)): S = Qh @ Kh^T / sqrt(DK) ----------------
__global__ void __launch_bounds__(256, 2) score_gemm_kernel()
{
    const float SCALE = 0.125f;
    int z = blockIdx.z;
    int b = z >> 3, h = z & 7;
    float acc[2][8][4] = {};
    const float* Ab = g_Q + (size_t)b * Lsz * Dsz + h * DKsz + (size_t)blockIdx.y * 128 * Dsz;
    const float* Bb = g_K + (size_t)b * Lsz * Dsz + h * DKsz + (size_t)blockIdx.x * 128 * Dsz;
    gemm_core<128, 128, true, 2, 8>(Ab, Dsz, Bb, Dsz, DKsz, acc);

    float* Cp = g_S + (size_t)z * Lsz * Lsz;
    int lane = threadIdx.x & 31, wid = threadIdx.x >> 5;
    int rowBase = blockIdx.y * 128 + (wid & 3) * 32 + (lane >> 2);
    int colBase = blockIdx.x * 128 + (wid >> 2) * 64 + 2 * (lane & 3);
    #pragma unroll
    for (int mt = 0; mt < 2; mt++)
        #pragma unroll
        for (int nt = 0; nt < 8; nt++) {
            int row = rowBase + mt * 16;
            int col = colBase + nt * 8;
            *(float2*)&Cp[(size_t)row * Lsz + col] =
                make_float2(acc[mt][nt][0] * SCALE, acc[mt][nt][1] * SCALE);
            *(float2*)&Cp[(size_t)(row + 8) * Lsz + col] =
                make_float2(acc[mt][nt][2] * SCALE, acc[mt][nt][3] * SCALE);
        }
}

// ---------------- ctx GEMM (NN per (b,h)): CTX = attn @ Vh ----------------
__global__ void __launch_bounds__(256, 2) ctx_gemm_kernel()
{
    int z = blockIdx.z;
    int b = z >> 3, h = z & 7;
    float acc[2][4][4] = {};
    const float* Ab = g_S + (size_t)z * Lsz * Lsz + (size_t)blockIdx.y * 128 * Lsz;
    const float* Bb = g_V + (size_t)b * Lsz * Dsz + h * DKsz;
    gemm_core<128, 64, false, 2, 4>(Ab, Lsz, Bb, Dsz, Lsz, acc);

    float* Cp = g_CTX + (size_t)b * Lsz * Dsz + h * DKsz;
    int lane = threadIdx.x & 31, wid = threadIdx.x >> 5;
    int rowBase = blockIdx.y * 128 + (wid & 3) * 32 + (lane >> 2);
    int colBase = (wid >> 2) * 32 + 2 * (lane & 3);
    #pragma unroll
    for (int mt = 0; mt < 2; mt++)
        #pragma unroll
        for (int nt = 0; nt < 4; nt++) {
            int row = rowBase + mt * 16;
            int col = colBase + nt * 8;
            *(float2*)&Cp[(size_t)row * Dsz + col] =
                make_float2(acc[mt][nt][0], acc[mt][nt][1]);
            *(float2*)&Cp[(size_t)(row + 8) * Dsz + col] =
                make_float2(acc[mt][nt][2], acc[mt][nt][3]);
        }
}

// ---------------- block reductions ----------------
__device__ __forceinline__ float blk_max(float v)
{
    __shared__ float sh[8];
    #pragma unroll
    for (int o = 16; o; o >>= 1) v = fmaxf(v, __shfl_xor_sync(0xffffffffu, v, o));
    if ((threadIdx.x & 31) == 0) sh[threadIdx.x >> 5] = v;
    __syncthreads();
    float r = sh[0];
    #pragma unroll
    for (int i = 1; i < 8; i++) r = fmaxf(r, sh[i]);
    __syncthreads();
    return r;
}

__device__ __forceinline__ float blk_sum(float v)
{
    __shared__ float sh[8];
    #pragma unroll
    for (int o = 16; o; o >>= 1) v += __shfl_xor_sync(0xffffffffu, v, o);
    if ((threadIdx.x & 31) == 0) sh[threadIdx.x >> 5] = v;
    __syncthreads();
    float r = 0.f;
    #pragma unroll
    for (int i = 0; i < 8; i++) r += sh[i];
    __syncthreads();
    return r;
}

// ---------------- fused softmax -> reweight -> softmax (row-wise, in place on g_S) ----------------
__global__ void softmax_kernel()
{
    int rid = blockIdx.x;
    int q = rid & (Lsz - 1);
    int z = rid >> 10;
    int b = z >> 3;
    float* Srow = g_S + (size_t)z * Lsz * Lsz + (size_t)q * Lsz;
    const float* Erow = g_EM + ((size_t)b * Lsz + q) * Lsz;
    float g = g_G[b * Lsz + q];
    int t = threadIdx.x;

    float x[4];
    #pragma unroll
    for (int i = 0; i < 4; i++) x[i] = Srow[t + i * 256];

    float mx = fmaxf(fmaxf(x[0], x[1]), fmaxf(x[2], x[3]));
    mx = blk_max(mx);

    float p[4], s = 0.f;
    #pragma unroll
    for (int i = 0; i < 4; i++) { p[i] = __expf(x[i] - mx); s += p[i]; }
    float Z = blk_sum(s);
    float invZ = 1.0f / Z;

    float c[4];
    #pragma unroll
    for (int i = 0; i < 4; i++) {
        float w = g + (1.0f - g) * Erow[t + i * 256];
        c[i] = p[i] * invZ * w;
    }

    float mx2 = fmaxf(fmaxf(c[0], c[1]), fmaxf(c[2], c[3]));
    mx2 = blk_max(mx2);

    float e2[4], s2 = 0.f;
    #pragma unroll
    for (int i = 0; i < 4; i++) { e2[i] = __expf(c[i] - mx2); s2 += e2[i]; }
    float Z2 = blk_sum(s2);
    float invZ2 = 1.0f / Z2;

    #pragma unroll
    for (int i = 0; i < 4; i++) Srow[t + i * 256] = e2[i] * invZ2;
}

// ---------------- gate ----------------
__global__ void gate_kernel(const float* __restrict__ query,
                            const float* __restrict__ gw,
                            const float* __restrict__ gb)
{
    int warp = (blockIdx.x * blockDim.x + threadIdx.x) >> 5;
    int lane = threadIdx.x & 31;
    if (warp >= Bsz * Lsz) return;
    const float* row = query + (size_t)warp * Dsz;
    float s = 0.f;
    for (int d = lane; d < Dsz; d += 32) s += row[d] * gw[d];
    #pragma unroll
    for (int o = 16; o; o >>= 1) s += __shfl_xor_sync(0xffffffffu, s, o);
    if (lane == 0) g_G[warp] = 1.0f / (1.0f + __expf(-(s + gb[0])));
}

// ---------------- launch ----------------
extern "C" void kernel_launch(void* const* d_in, const int* in_sizes, int n_in,
                              void* d_out, int out_size)
{
    const float* query   = (const float*)d_in[0];
    const float* key     = (const float*)d_in[1];
    const float* value   = (const float*)d_in[2];
    const float* wq_w    = (const float*)d_in[3];
    const float* wq_b    = (const float*)d_in[4];
    const float* wk_w    = (const float*)d_in[5];
    const float* wk_b    = (const float*)d_in[6];
    const float* wv_w    = (const float*)d_in[7];
    const float* wv_b    = (const float*)d_in[8];
    const float* dense_w = (const float*)d_in[9];
    const float* dense_b = (const float*)d_in[10];
    const float* gate_w  = (const float*)d_in[11];
    const float* gate_b  = (const float*)d_in[12];
    const float* mp_wq_w = (const float*)d_in[13];
    const float* mp_wq_b = (const float*)d_in[14];
    const float* mp_wk_w = (const float*)d_in[15];
    const float* mp_wk_b = (const float*)d_in[16];

    float* out   = (float*)d_out;
    float* m_out = out + (size_t)Bsz * Lsz * Dsz;

    float *pQ, *pK, *pV, *pQP, *pKP, *pCTX;
    cudaGetSymbolAddress((void**)&pQ,   g_Q);
    cudaGetSymbolAddress((void**)&pK,   g_K);
    cudaGetSymbolAddress((void**)&pV,   g_V);
    cudaGetSymbolAddress((void**)&pQP,  g_QP);
    cudaGetSymbolAddress((void**)&pKP,  g_KP);
    cudaGetSymbolAddress((void**)&pCTX, g_CTX);

    dim3 t256(256);

    // 5 projection GEMMs in a single launch
    ProjArgs pa;
    pa.A[0] = query; pa.W[0] = wq_w;    pa.bias[0] = wq_b;    pa.C[0] = pQ;
    pa.A[1] = key;   pa.W[1] = wk_w;    pa.bias[1] = wk_b;    pa.C[1] = pK;
    pa.A[2] = value; pa.W[2] = wv_w;    pa.bias[2] = wv_b;    pa.C[2] = pV;
    pa.A[3] = query; pa.W[3] = mp_wq_w; pa.bias[3] = mp_wq_b; pa.C[3] = pQP;
    pa.A[4] = key;   pa.W[4] = mp_wk_w; pa.bias[4] = mp_wk_b; pa.C[4] = pKP;
    proj_gemm_kernel<<<dim3(4, 32, 5), t256>>>(pa, Dsz, Dsz);

    gate_kernel<<<(Bsz * Lsz * 32) / 256, 256>>>(query, gate_w, gate_b);

    m_gemm_kernel<<<dim3(8, 8, Bsz), t256>>>(m_out);

    score_gemm_kernel<<<dim3(8, 8, Bsz * Hsz), t256>>>();

    softmax_kernel<<<Bsz * Hsz * Lsz, 256>>>();

    ctx_gemm_kernel<<<dim3(1, 8, Bsz * Hsz), t256>>>();

    // dense output projection (single-entry batch)
    ProjArgs da;
    da.A[0] = pCTX; da.W[0] = dense_w; da.bias[0] = dense_b; da.C[0] = out;
    proj_gemm_kernel<<<dim3(4, 32, 1), t256>>>(da, Dsz, Dsz);
}